// round 1
// baseline (speedup 1.0000x reference)
#include <cuda_runtime.h>
#include <cuda_bf16.h>
#include <math.h>

#define Bsz  16384
#define EDIM 128
#define HIST 50
#define KC   1920   // compact K for MLP1 (zero columns of c removed)
#define EPSF 1e-5f

// ---------------- scratch (device globals; no allocation allowed) ----------
__device__ float g_mm_pre[Bsz * EDIM];               //  8.4 MB
__device__ float g_xs[Bsz * 6 * EDIM];               // 50 MB
__device__ float g_xw[Bsz * 6 * EDIM];               // 50 MB
__device__ float g_c[(size_t)Bsz * KC];              // 126 MB
__device__ float g_h1[Bsz * 512];                    // 33.5 MB
__device__ float g_h2[Bsz * 256];                    // 16.8 MB
__device__ float g_W1c[KC * 512];                    //  3.9 MB
__device__ float g_bn1_s[512], g_bn1_t[512];
__device__ float g_bn2_s[256], g_bn2_t[256];

// non-zero field pairs (original pair indices 5..14 of triu(6, k=1))
__constant__ int c_I[10] = {1,1,1,1,2,2,2,3,3,4};
__constant__ int c_J[10] = {2,3,4,5,3,4,5,4,5,5};

// ---------------- prep: fold BN (+ MLP bias) and compact W1 ----------------
__global__ void prep_bn_kernel(const float* __restrict__ b1, const float* __restrict__ g1,
                               const float* __restrict__ be1, const float* __restrict__ rm1,
                               const float* __restrict__ rv1,
                               const float* __restrict__ b2, const float* __restrict__ g2,
                               const float* __restrict__ be2, const float* __restrict__ rm2,
                               const float* __restrict__ rv2) {
    int i = blockIdx.x * blockDim.x + threadIdx.x;
    if (i < 512) {
        float s = g1[i] * rsqrtf(rv1[i] + EPSF);
        g_bn1_s[i] = s;
        g_bn1_t[i] = (b1[i] - rm1[i]) * s + be1[i];
    }
    if (i < 256) {
        float s = g2[i] * rsqrtf(rv2[i] + EPSF);
        g_bn2_s[i] = s;
        g_bn2_t[i] = (b2[i] - rm2[i]) * s + be2[i];
    }
}

__global__ void prep_w1_kernel(const float* __restrict__ W1) {
    // compact rows: r in [0,640) <- orig row r+128 ; r in [640,1920) <- orig row r+768
    int idx = blockIdx.x * blockDim.x + threadIdx.x;   // over KC*512
    if (idx >= KC * 512) return;
    int r = idx >> 9;           // /512
    int n = idx & 511;
    int orig = (r < 640) ? (r + 128) : (r + 768);
    g_W1c[idx] = W1[(size_t)orig * 512 + n];
}

// ---------------- generic fp32 tiled GEMM: C = act(scale*(A@B) + shift) ----
// A: MxK row-major, B: KxN row-major, C: MxN. M%128==0, N%64==0, K%16==0.
template <bool RELU>
__global__ void gemm_f32(const float* __restrict__ A, const float* __restrict__ Bm,
                         float* __restrict__ C, int M, int N, int K,
                         const float* __restrict__ scale, const float* __restrict__ shift) {
    constexpr int BM = 128, BN = 64, BK = 16, TM = 8, TN = 4;
    constexpr int THREADS = (BM / TM) * (BN / TN);   // 256
    __shared__ float As[BK][BM];
    __shared__ float Bs[BK][BN];

    const int tid  = threadIdx.x;
    const int brow = blockIdx.y * BM;
    const int bcol = blockIdx.x * BN;
    const int tx   = tid % (BN / TN);   // 0..15
    const int ty   = tid / (BN / TN);   // 0..15

    float acc[TM][TN] = {};

    for (int kt = 0; kt < K; kt += BK) {
        // load A tile (BM x BK) as float4 along K, store transposed
        #pragma unroll
        for (int v = tid; v < BM * BK / 4; v += THREADS) {
            int r  = v / (BK / 4);
            int c4 = (v % (BK / 4)) * 4;
            float4 f = *(const float4*)&A[(size_t)(brow + r) * K + kt + c4];
            As[c4 + 0][r] = f.x;
            As[c4 + 1][r] = f.y;
            As[c4 + 2][r] = f.z;
            As[c4 + 3][r] = f.w;
        }
        // load B tile (BK x BN)
        #pragma unroll
        for (int v = tid; v < BK * BN / 4; v += THREADS) {
            int r  = v / (BN / 4);
            int c4 = (v % (BN / 4)) * 4;
            *(float4*)&Bs[r][c4] = *(const float4*)&Bm[(size_t)(kt + r) * N + bcol + c4];
        }
        __syncthreads();

        #pragma unroll
        for (int k = 0; k < BK; k++) {
            float regM[TM], regN[TN];
            #pragma unroll
            for (int i = 0; i < TM; i++) regM[i] = As[k][ty * TM + i];
            #pragma unroll
            for (int j = 0; j < TN; j++) regN[j] = Bs[k][tx * TN + j];
            #pragma unroll
            for (int i = 0; i < TM; i++)
                #pragma unroll
                for (int j = 0; j < TN; j++)
                    acc[i][j] += regM[i] * regN[j];
        }
        __syncthreads();
    }

    #pragma unroll
    for (int i = 0; i < TM; i++) {
        int row = brow + ty * TM + i;
        #pragma unroll
        for (int j = 0; j < TN; j++) {
            int col = bcol + tx * TN + j;
            float v = acc[i][j];
            if (scale) v *= scale[col];
            if (shift) v += shift[col];
            if (RELU)  v = fmaxf(v, 0.0f);
            C[(size_t)row * N + col] = v;
        }
    }
}

// ---------------- per-row feature construction ------------------------------
__device__ __forceinline__ float block_sum_128(float v, float* sred) {
    int lane = threadIdx.x & 31, wid = threadIdx.x >> 5;
    #pragma unroll
    for (int o = 16; o; o >>= 1) v += __shfl_xor_sync(0xffffffffu, v, o);
    if (lane == 0) sred[wid] = v;
    __syncthreads();
    float s = sred[0] + sred[1] + sred[2] + sred[3];
    __syncthreads();
    return s;
}

__global__ void features_kernel(const int* __restrict__ item_id,
                                const int* __restrict__ likes,
                                const int* __restrict__ views,
                                const int* __restrict__ item_seq,
                                const float* __restrict__ item_emb,
                                const float* __restrict__ cate_emb,
                                const float* __restrict__ ln_g,
                                const float* __restrict__ ln_b,
                                const float* __restrict__ se_W1,
                                const float* __restrict__ se_b1,
                                const float* __restrict__ se_W2,
                                const float* __restrict__ se_b2) {
    __shared__ float sred[4];
    const int b = blockIdx.x;
    const int e = threadIdx.x;

    // mm projection result -> LayerNorm -> ReLU
    float mmv = g_mm_pre[(size_t)b * EDIM + e];
    float mu  = block_sum_128(mmv, sred) * (1.0f / 128.0f);
    float d   = mmv - mu;
    float var = block_sum_128(d * d, sred) * (1.0f / 128.0f);
    float mm  = fmaxf(d * rsqrtf(var + EPSF) * ln_g[e] + ln_b[e], 0.0f);

    // gathers
    int   id   = item_id[b];
    float item = (id == 0) ? 0.0f : item_emb[(size_t)id * EDIM + e];
    float like = cate_emb[(size_t)likes[b] * EDIM + e];
    float view = cate_emb[(size_t)views[b] * EDIM + e];

    // masked mean pooling over history
    float hsum = 0.0f;
    int   cnt  = 0;
    #pragma unroll 5
    for (int t = 0; t < HIST; t++) {
        int s = item_seq[(size_t)b * HIST + t];
        if (s != 0) { hsum += item_emb[(size_t)s * EDIM + e]; cnt++; }
    }
    float hist = hsum / (float)(cnt > 1 ? cnt : 1);

    float x[6] = {0.0f, like, view, item, mm, hist};

    // SENet: z = mean over E per field
    float z[6];
    z[0] = 0.0f;
    #pragma unroll
    for (int f = 1; f < 6; f++) z[f] = block_sum_128(x[f], sred) * (1.0f / 128.0f);

    // tiny MLP (redundantly per-thread; trivially cheap)
    float w[6];
    {
        float h[3];
        #pragma unroll
        for (int j = 0; j < 3; j++) {
            float s = se_b1[j];
            #pragma unroll
            for (int f = 0; f < 6; f++) s += z[f] * se_W1[f * 3 + j];
            h[j] = fmaxf(s, 0.0f);
        }
        #pragma unroll
        for (int f = 0; f < 6; f++) {
            float s = se_b2[f];
            #pragma unroll
            for (int j = 0; j < 3; j++) s += h[j] * se_W2[j * 6 + f];
            w[f] = 1.0f / (1.0f + expf(-s));
        }
    }

    // write xs (all 6 fields) and the xs part of compact c (fields 1..5)
    #pragma unroll
    for (int f = 0; f < 6; f++) {
        float xv = x[f] * w[f];
        g_xs[((size_t)b * 6 + f) * EDIM + e] = xv;
        if (f >= 1)
            g_c[(size_t)b * KC + (f - 1) * EDIM + e] = xv;
    }
}

// ---------------- bilinear pair products (non-zero pairs only) -------------
__global__ void pairs_kernel() {
    int idx = blockIdx.x * blockDim.x + threadIdx.x;   // over Bsz*10*128
    if (idx >= Bsz * 10 * EDIM) return;
    int e  = idx & 127;
    int pr = (idx >> 7) % 10;
    int b  = idx / (10 * EDIM);
    int i  = c_I[pr], j = c_J[pr];
    float v = g_xs[((size_t)b * 6 + i) * EDIM + e] *
              g_xw[((size_t)b * 6 + j) * EDIM + e];
    g_c[(size_t)b * KC + 640 + pr * EDIM + e] = v;
}

// ---------------- final layer: dot(256) + bias + sigmoid -------------------
__global__ void final_kernel(const float* __restrict__ W3, const float* __restrict__ b3,
                             float* __restrict__ out) {
    int gwarp = (blockIdx.x * blockDim.x + threadIdx.x) >> 5;
    int lane  = threadIdx.x & 31;
    if (gwarp >= Bsz) return;
    float s = 0.0f;
    #pragma unroll
    for (int k = lane; k < 256; k += 32)
        s += g_h2[(size_t)gwarp * 256 + k] * W3[k];
    #pragma unroll
    for (int o = 16; o; o >>= 1) s += __shfl_xor_sync(0xffffffffu, s, o);
    if (lane == 0) out[gwarp] = 1.0f / (1.0f + expf(-(s + b3[0])));
}

// ---------------- launch ----------------------------------------------------
extern "C" void kernel_launch(void* const* d_in, const int* in_sizes, int n_in,
                              void* d_out, int out_size) {
    const int*   item_id   = (const int*)  d_in[0];
    const float* x_d128    = (const float*)d_in[1];
    const int*   likes     = (const int*)  d_in[2];
    const int*   views     = (const int*)  d_in[3];
    const int*   item_seq  = (const int*)  d_in[4];
    const float* item_emb  = (const float*)d_in[5];
    const float* cate_emb  = (const float*)d_in[6];
    const float* mm_W      = (const float*)d_in[7];
    const float* mm_b      = (const float*)d_in[8];
    const float* ln_g      = (const float*)d_in[9];
    const float* ln_b      = (const float*)d_in[10];
    const float* se_W1     = (const float*)d_in[11];
    const float* se_b1     = (const float*)d_in[12];
    const float* se_W2     = (const float*)d_in[13];
    const float* se_b2     = (const float*)d_in[14];
    const float* bi_W      = (const float*)d_in[15];
    const float* mlp_W1    = (const float*)d_in[16];
    const float* mlp_b1    = (const float*)d_in[17];
    const float* bn1_g     = (const float*)d_in[18];
    const float* bn1_b     = (const float*)d_in[19];
    const float* bn1_rm    = (const float*)d_in[20];
    const float* bn1_rv    = (const float*)d_in[21];
    const float* mlp_W2    = (const float*)d_in[22];
    const float* mlp_b2    = (const float*)d_in[23];
    const float* bn2_g     = (const float*)d_in[24];
    const float* bn2_b     = (const float*)d_in[25];
    const float* bn2_rm    = (const float*)d_in[26];
    const float* bn2_rv    = (const float*)d_in[27];
    const float* mlp_W3    = (const float*)d_in[28];
    const float* mlp_b3    = (const float*)d_in[29];
    float*       out       = (float*)d_out;

    float *p_mm_pre, *p_xs, *p_xw, *p_c, *p_h1, *p_h2, *p_W1c;
    float *p_bn1_s, *p_bn1_t, *p_bn2_s, *p_bn2_t;
    cudaGetSymbolAddress((void**)&p_mm_pre, g_mm_pre);
    cudaGetSymbolAddress((void**)&p_xs,     g_xs);
    cudaGetSymbolAddress((void**)&p_xw,     g_xw);
    cudaGetSymbolAddress((void**)&p_c,      g_c);
    cudaGetSymbolAddress((void**)&p_h1,     g_h1);
    cudaGetSymbolAddress((void**)&p_h2,     g_h2);
    cudaGetSymbolAddress((void**)&p_W1c,    g_W1c);
    cudaGetSymbolAddress((void**)&p_bn1_s,  g_bn1_s);
    cudaGetSymbolAddress((void**)&p_bn1_t,  g_bn1_t);
    cudaGetSymbolAddress((void**)&p_bn2_s,  g_bn2_s);
    cudaGetSymbolAddress((void**)&p_bn2_t,  g_bn2_t);

    // prep
    prep_bn_kernel<<<1, 512>>>(mlp_b1, bn1_g, bn1_b, bn1_rm, bn1_rv,
                               mlp_b2, bn2_g, bn2_b, bn2_rm, bn2_rv);
    prep_w1_kernel<<<(KC * 512 + 255) / 256, 256>>>(mlp_W1);

    // mm_pre = item_emb_d128 @ mm_W + mm_b
    gemm_f32<false><<<dim3(128 / 64, Bsz / 128), 256>>>(
        x_d128, mm_W, p_mm_pre, Bsz, 128, 128, nullptr, mm_b);

    // per-row features -> xs, c[:, 0:640]
    features_kernel<<<Bsz, 128>>>(item_id, likes, views, item_seq,
                                  item_emb, cate_emb, ln_g, ln_b,
                                  se_W1, se_b1, se_W2, se_b2);

    // xw = xs @ bi_W   (M = B*6)
    gemm_f32<false><<<dim3(128 / 64, (Bsz * 6) / 128), 256>>>(
        p_xs, bi_W, p_xw, Bsz * 6, 128, 128, nullptr, nullptr);

    // pair products -> c[:, 640:1920]
    pairs_kernel<<<(Bsz * 10 * EDIM + 255) / 256, 256>>>();

    // h1 = relu(bn1(c @ W1c + b1))    (K = 1920 compact)
    gemm_f32<true><<<dim3(512 / 64, Bsz / 128), 256>>>(
        p_c, p_W1c, p_h1, Bsz, 512, KC, p_bn1_s, p_bn1_t);

    // h2 = relu(bn2(h1 @ W2 + b2))
    gemm_f32<true><<<dim3(256 / 64, Bsz / 128), 256>>>(
        p_h1, mlp_W2, p_h2, Bsz, 256, 512, p_bn2_s, p_bn2_t);

    // logits -> sigmoid
    final_kernel<<<(Bsz * 32 + 255) / 256, 256>>>(mlp_W3, mlp_b3, out);
}

// round 3
// speedup vs baseline: 1.5913x; 1.5913x over previous
#include <cuda_runtime.h>
#include <cuda_bf16.h>
#include <math.h>
#include <stdint.h>

#define Bsz  16384
#define EDIM 128
#define HIST 50
#define KC   1920   // compact K for MLP1 (zero columns of c removed)
#define EPSF 1e-5f

// ---------------- scratch (device globals; no allocation allowed) ----------
__device__ float g_mm_pre[Bsz * EDIM];                       //  8.4 MB
__device__ float g_xs[Bsz * 6 * EDIM];                       // 50 MB
__device__ float g_xw[Bsz * 6 * EDIM];                       // 50 MB
__device__ __nv_bfloat16 g_c_hi[(size_t)Bsz * KC];           // 63 MB
__device__ __nv_bfloat16 g_c_lo[(size_t)Bsz * KC];           // 63 MB
__device__ __nv_bfloat16 g_h1_hi[Bsz * 512];                 // 16.8 MB
__device__ __nv_bfloat16 g_h1_lo[Bsz * 512];                 // 16.8 MB
__device__ float g_h2[Bsz * 256];                            // 16.8 MB
__device__ __nv_bfloat16 g_W1T_hi[512 * KC];                 //  2 MB (N-major: [512][1920])
__device__ __nv_bfloat16 g_W1T_lo[512 * KC];
__device__ __nv_bfloat16 g_W2T_hi[256 * 512];                // [256][512]
__device__ __nv_bfloat16 g_W2T_lo[256 * 512];
__device__ float g_bn1_s[512], g_bn1_t[512];
__device__ float g_bn2_s[256], g_bn2_t[256];

// non-zero field pairs (original pair indices 5..14 of triu(6, k=1))
__constant__ int c_I[10] = {1,1,1,1,2,2,2,3,3,4};
__constant__ int c_J[10] = {2,3,4,5,3,4,5,4,5,5};

// ================= PTX helpers (non-arch-specific only) =====================
__device__ __forceinline__ uint32_t smem_u32(const void* p) {
    uint32_t a;
    asm("{ .reg .u64 t; cvta.to.shared.u64 t, %1; cvt.u32.u64 %0, t; }"
        : "=r"(a) : "l"(p));
    return a;
}
__device__ __forceinline__ void cp_async16(uint32_t dst, const void* src) {
    asm volatile("cp.async.cg.shared.global [%0], [%1], 16;" :: "r"(dst), "l"(src));
}
#define CP_COMMIT() asm volatile("cp.async.commit_group;" ::: "memory")
#define CP_WAIT0()  asm volatile("cp.async.wait_group 0;" ::: "memory")
#define CP_WAIT1()  asm volatile("cp.async.wait_group 1;" ::: "memory")

__device__ __forceinline__ void ldsm_x4(uint32_t* r, uint32_t addr) {
    asm volatile("ldmatrix.sync.aligned.m8n8.x4.shared.b16 {%0,%1,%2,%3}, [%4];"
                 : "=r"(r[0]), "=r"(r[1]), "=r"(r[2]), "=r"(r[3]) : "r"(addr));
}
#define MMA_BF16(c, a, b0v, b1v) \
    asm volatile("mma.sync.aligned.m16n8k16.row.col.f32.bf16.bf16.f32 " \
        "{%0,%1,%2,%3}, {%4,%5,%6,%7}, {%8,%9}, {%0,%1,%2,%3};" \
        : "+f"((c)[0]), "+f"((c)[1]), "+f"((c)[2]), "+f"((c)[3]) \
        : "r"((a)[0]), "r"((a)[1]), "r"((a)[2]), "r"((a)[3]), "r"(b0v), "r"(b1v))

// ---------------- prep: fold BN (+ MLP bias) ------------------------------
__global__ void prep_bn_kernel(const float* __restrict__ b1, const float* __restrict__ g1,
                               const float* __restrict__ be1, const float* __restrict__ rm1,
                               const float* __restrict__ rv1,
                               const float* __restrict__ b2, const float* __restrict__ g2,
                               const float* __restrict__ be2, const float* __restrict__ rm2,
                               const float* __restrict__ rv2) {
    int i = blockIdx.x * blockDim.x + threadIdx.x;
    if (i < 512) {
        float s = g1[i] * rsqrtf(rv1[i] + EPSF);
        g_bn1_s[i] = s;
        g_bn1_t[i] = (b1[i] - rm1[i]) * s + be1[i];
    }
    if (i < 256) {
        float s = g2[i] * rsqrtf(rv2[i] + EPSF);
        g_bn2_s[i] = s;
        g_bn2_t[i] = (b2[i] - rm2[i]) * s + be2[i];
    }
}

// W1: compact rows + transpose to [N=512][K=1920], split bf16 hi/lo
__global__ void prep_w1_kernel(const float* __restrict__ W1) {
    int idx = blockIdx.x * blockDim.x + threadIdx.x;   // over 512*KC
    if (idx >= 512 * KC) return;
    int n = idx / KC;
    int k = idx % KC;
    int orig = (k < 640) ? (k + 128) : (k + 768);
    float v = W1[(size_t)orig * 512 + n];
    __nv_bfloat16 h = __float2bfloat16_rn(v);
    g_W1T_hi[idx] = h;
    g_W1T_lo[idx] = __float2bfloat16_rn(v - __bfloat162float(h));
}

// W2: transpose [512][256] -> [256][512], split bf16
__global__ void prep_w2_kernel(const float* __restrict__ W2) {
    int idx = blockIdx.x * blockDim.x + threadIdx.x;   // over 256*512
    if (idx >= 256 * 512) return;
    int n = idx / 512;
    int k = idx % 512;
    float v = W2[(size_t)k * 256 + n];
    __nv_bfloat16 h = __float2bfloat16_rn(v);
    g_W2T_hi[idx] = h;
    g_W2T_lo[idx] = __float2bfloat16_rn(v - __bfloat162float(h));
}

// ---------------- generic fp32 tiled GEMM (for small mm / xw GEMMs) --------
template <bool RELU>
__global__ void gemm_f32(const float* __restrict__ A, const float* __restrict__ Bm,
                         float* __restrict__ C, int M, int N, int K,
                         const float* __restrict__ scale, const float* __restrict__ shift) {
    constexpr int BM = 128, BN = 64, BK = 16, TM = 8, TN = 4;
    constexpr int THREADS = (BM / TM) * (BN / TN);   // 256
    __shared__ float As[BK][BM];
    __shared__ float Bs[BK][BN];

    const int tid  = threadIdx.x;
    const int brow = blockIdx.y * BM;
    const int bcol = blockIdx.x * BN;
    const int tx   = tid % (BN / TN);
    const int ty   = tid / (BN / TN);

    float acc[TM][TN] = {};

    for (int kt = 0; kt < K; kt += BK) {
        #pragma unroll
        for (int v = tid; v < BM * BK / 4; v += THREADS) {
            int r  = v / (BK / 4);
            int c4 = (v % (BK / 4)) * 4;
            float4 f = *(const float4*)&A[(size_t)(brow + r) * K + kt + c4];
            As[c4 + 0][r] = f.x;
            As[c4 + 1][r] = f.y;
            As[c4 + 2][r] = f.z;
            As[c4 + 3][r] = f.w;
        }
        #pragma unroll
        for (int v = tid; v < BK * BN / 4; v += THREADS) {
            int r  = v / (BN / 4);
            int c4 = (v % (BN / 4)) * 4;
            *(float4*)&Bs[r][c4] = *(const float4*)&Bm[(size_t)(kt + r) * N + bcol + c4];
        }
        __syncthreads();

        #pragma unroll
        for (int k = 0; k < BK; k++) {
            float regM[TM], regN[TN];
            #pragma unroll
            for (int i = 0; i < TM; i++) regM[i] = As[k][ty * TM + i];
            #pragma unroll
            for (int j = 0; j < TN; j++) regN[j] = Bs[k][tx * TN + j];
            #pragma unroll
            for (int i = 0; i < TM; i++)
                #pragma unroll
                for (int j = 0; j < TN; j++)
                    acc[i][j] += regM[i] * regN[j];
        }
        __syncthreads();
    }

    #pragma unroll
    for (int i = 0; i < TM; i++) {
        int row = brow + ty * TM + i;
        #pragma unroll
        for (int j = 0; j < TN; j++) {
            int col = bcol + tx * TN + j;
            float v = acc[i][j];
            if (scale) v *= scale[col];
            if (shift) v += shift[col];
            if (RELU)  v = fmaxf(v, 0.0f);
            C[(size_t)row * N + col] = v;
        }
    }
}

// ======== mma.sync bf16 split-3 GEMM: C = relu(scale*(A@B^T)+shift) =========
// A (hi/lo bf16): M x K row-major, K-contiguous.
// B (hi/lo bf16): Ntot x K row-major (transposed weights), K-contiguous.
// CTA tile 128x128, 8 warps (4m x 2n), BK=32, 2-stage cp.async pipeline.
#define MMG_LDS    40                       // bf16 elems per smem row (32 + 8 pad)
#define MMG_ARR    (128 * MMG_LDS * 2)      // 10240 B per operand tile
#define MMG_STAGE  (4 * MMG_ARR)            // 40960 B
#define MMG_SMEM   (2 * MMG_STAGE)          // 81920 B

template <bool OUT_SPLIT>
__global__ void __launch_bounds__(256, 1)
mma_gemm(const __nv_bfloat16* __restrict__ Ah, const __nv_bfloat16* __restrict__ Al,
         const __nv_bfloat16* __restrict__ Bh, const __nv_bfloat16* __restrict__ Bl,
         int K,
         const float* __restrict__ scale, const float* __restrict__ shift,
         float* __restrict__ Cf, __nv_bfloat16* __restrict__ Chi,
         __nv_bfloat16* __restrict__ Clo, int ldC) {
    extern __shared__ char smem[];
    const uint32_t sbase = smem_u32(smem);
    const int tid    = threadIdx.x;
    const int wid    = tid >> 5;
    const int lane   = tid & 31;
    const int warp_m = wid & 3;          // 0..3 -> 32 rows each
    const int warp_n = wid >> 2;         // 0..1 -> 64 cols each
    const int m0     = blockIdx.y * 128;
    const int bcol   = blockIdx.x * 128;
    const int nch    = K >> 5;           // BK = 32

    float acc[2][8][4];
    #pragma unroll
    for (int a = 0; a < 2; a++)
        #pragma unroll
        for (int b = 0; b < 8; b++)
            #pragma unroll
            for (int c = 0; c < 4; c++) acc[a][b][c] = 0.0f;

    // ---- stage loader: 2048 16B-chunks, 8 per thread ----
    auto load_stage = [&](int st, int k0) {
        const uint32_t sdst = sbase + st * MMG_STAGE;
        #pragma unroll
        for (int i = 0; i < 8; i++) {
            int c   = tid + i * 256;
            int a   = c >> 9;            // operand array 0..3 (uniform per i)
            int idx = c & 511;
            int r   = idx >> 2;
            int cc  = idx & 3;
            const __nv_bfloat16* g;
            if (a < 2) {
                g = (a == 0 ? Ah : Al) + (size_t)(m0 + r) * K + k0 + cc * 8;
            } else {
                g = (a == 2 ? Bh : Bl) + (size_t)(bcol + r) * K + k0 + cc * 8;
            }
            cp_async16(sdst + a * MMG_ARR + r * (MMG_LDS * 2) + cc * 16, g);
        }
        CP_COMMIT();
    };

    load_stage(0, 0);

    const int lrow = lane & 15;
    const int lcol = lane >> 4;

    for (int ch = 0; ch < nch; ch++) {
        if (ch + 1 < nch) {
            load_stage((ch + 1) & 1, (ch + 1) << 5);
            CP_WAIT1();
        } else {
            CP_WAIT0();
        }
        __syncthreads();

        const uint32_t sa_hi = sbase + (ch & 1) * MMG_STAGE;
        const uint32_t sa_lo = sa_hi + MMG_ARR;
        const uint32_t sb_hi = sa_hi + 2 * MMG_ARR;
        const uint32_t sb_lo = sa_hi + 3 * MMG_ARR;

        #pragma unroll
        for (int kk = 0; kk < 2; kk++) {
            uint32_t ah[2][4], al[2][4];
            #pragma unroll
            for (int mt = 0; mt < 2; mt++) {
                uint32_t off = (uint32_t)((warp_m * 32 + mt * 16 + lrow) * (MMG_LDS * 2)
                               + kk * 32 + lcol * 16);
                ldsm_x4(ah[mt], sa_hi + off);
                ldsm_x4(al[mt], sa_lo + off);
            }
            uint32_t bh[4][4], bl[4][4];
            #pragma unroll
            for (int q = 0; q < 4; q++) {
                uint32_t off = (uint32_t)((warp_n * 64 + q * 16 + lrow) * (MMG_LDS * 2)
                               + kk * 32 + lcol * 16);
                ldsm_x4(bh[q], sb_hi + off);
                ldsm_x4(bl[q], sb_lo + off);
            }
            #pragma unroll
            for (int mt = 0; mt < 2; mt++) {
                #pragma unroll
                for (int nt = 0; nt < 8; nt++) {
                    const int q  = nt >> 1;
                    const int sl = nt & 1;
                    MMA_BF16(acc[mt][nt], ah[mt], bh[q][sl], bh[q][sl + 2]); // hi*hi
                    MMA_BF16(acc[mt][nt], ah[mt], bl[q][sl], bl[q][sl + 2]); // hi*lo
                    MMA_BF16(acc[mt][nt], al[mt], bh[q][sl], bh[q][sl + 2]); // lo*hi
                }
            }
        }
        __syncthreads();
    }

    // ---- fused epilogue: scale/shift (BN+bias) + ReLU ----
    #pragma unroll
    for (int mt = 0; mt < 2; mt++) {
        const int rbase = m0 + warp_m * 32 + mt * 16 + (lane >> 2);
        #pragma unroll
        for (int nt = 0; nt < 8; nt++) {
            const int col = bcol + warp_n * 64 + nt * 8 + (lane & 3) * 2;
            const float s0 = scale[col], s1 = scale[col + 1];
            const float t0 = shift[col], t1 = shift[col + 1];
            #pragma unroll
            for (int h = 0; h < 2; h++) {
                const size_t row = (size_t)(rbase + h * 8);
                float v0 = fmaxf(acc[mt][nt][h * 2 + 0] * s0 + t0, 0.0f);
                float v1 = fmaxf(acc[mt][nt][h * 2 + 1] * s1 + t1, 0.0f);
                if (OUT_SPLIT) {
                    __nv_bfloat16 h0 = __float2bfloat16_rn(v0);
                    __nv_bfloat16 h1 = __float2bfloat16_rn(v1);
                    __nv_bfloat162 hv; hv.x = h0; hv.y = h1;
                    __nv_bfloat162 lv;
                    lv.x = __float2bfloat16_rn(v0 - __bfloat162float(h0));
                    lv.y = __float2bfloat16_rn(v1 - __bfloat162float(h1));
                    *(__nv_bfloat162*)&Chi[row * ldC + col] = hv;
                    *(__nv_bfloat162*)&Clo[row * ldC + col] = lv;
                } else {
                    float2 fv; fv.x = v0; fv.y = v1;
                    *(float2*)&Cf[row * ldC + col] = fv;
                }
            }
        }
    }
}

// ---------------- per-row feature construction ------------------------------
__device__ __forceinline__ float block_sum_128(float v, float* sred) {
    int lane = threadIdx.x & 31, wid = threadIdx.x >> 5;
    #pragma unroll
    for (int o = 16; o; o >>= 1) v += __shfl_xor_sync(0xffffffffu, v, o);
    if (lane == 0) sred[wid] = v;
    __syncthreads();
    float s = sred[0] + sred[1] + sred[2] + sred[3];
    __syncthreads();
    return s;
}

__global__ void features_kernel(const int* __restrict__ item_id,
                                const int* __restrict__ likes,
                                const int* __restrict__ views,
                                const int* __restrict__ item_seq,
                                const float* __restrict__ item_emb,
                                const float* __restrict__ cate_emb,
                                const float* __restrict__ ln_g,
                                const float* __restrict__ ln_b,
                                const float* __restrict__ se_W1,
                                const float* __restrict__ se_b1,
                                const float* __restrict__ se_W2,
                                const float* __restrict__ se_b2) {
    __shared__ float sred[4];
    const int b = blockIdx.x;
    const int e = threadIdx.x;

    float mmv = g_mm_pre[(size_t)b * EDIM + e];
    float mu  = block_sum_128(mmv, sred) * (1.0f / 128.0f);
    float d   = mmv - mu;
    float var = block_sum_128(d * d, sred) * (1.0f / 128.0f);
    float mm  = fmaxf(d * rsqrtf(var + EPSF) * ln_g[e] + ln_b[e], 0.0f);

    int   id   = item_id[b];
    float item = (id == 0) ? 0.0f : item_emb[(size_t)id * EDIM + e];
    float like = cate_emb[(size_t)likes[b] * EDIM + e];
    float view = cate_emb[(size_t)views[b] * EDIM + e];

    float hsum = 0.0f;
    int   cnt  = 0;
    #pragma unroll 5
    for (int t = 0; t < HIST; t++) {
        int s = item_seq[(size_t)b * HIST + t];
        if (s != 0) { hsum += item_emb[(size_t)s * EDIM + e]; cnt++; }
    }
    float hist = hsum / (float)(cnt > 1 ? cnt : 1);

    float x[6] = {0.0f, like, view, item, mm, hist};

    float z[6];
    z[0] = 0.0f;
    #pragma unroll
    for (int f = 1; f < 6; f++) z[f] = block_sum_128(x[f], sred) * (1.0f / 128.0f);

    float w[6];
    {
        float h[3];
        #pragma unroll
        for (int j = 0; j < 3; j++) {
            float s = se_b1[j];
            #pragma unroll
            for (int f = 0; f < 6; f++) s += z[f] * se_W1[f * 3 + j];
            h[j] = fmaxf(s, 0.0f);
        }
        #pragma unroll
        for (int f = 0; f < 6; f++) {
            float s = se_b2[f];
            #pragma unroll
            for (int j = 0; j < 3; j++) s += h[j] * se_W2[j * 6 + f];
            w[f] = 1.0f / (1.0f + expf(-s));
        }
    }

    #pragma unroll
    for (int f = 0; f < 6; f++) {
        float xv = x[f] * w[f];
        g_xs[((size_t)b * 6 + f) * EDIM + e] = xv;
        if (f >= 1) {
            size_t ci = (size_t)b * KC + (f - 1) * EDIM + e;
            __nv_bfloat16 h = __float2bfloat16_rn(xv);
            g_c_hi[ci] = h;
            g_c_lo[ci] = __float2bfloat16_rn(xv - __bfloat162float(h));
        }
    }
}

// ---------------- bilinear pair products (non-zero pairs only) -------------
__global__ void pairs_kernel() {
    int idx = blockIdx.x * blockDim.x + threadIdx.x;   // over Bsz*10*128
    if (idx >= Bsz * 10 * EDIM) return;
    int e  = idx & 127;
    int pr = (idx >> 7) % 10;
    int b  = idx / (10 * EDIM);
    int i  = c_I[pr], j = c_J[pr];
    float v = g_xs[((size_t)b * 6 + i) * EDIM + e] *
              g_xw[((size_t)b * 6 + j) * EDIM + e];
    size_t ci = (size_t)b * KC + 640 + pr * EDIM + e;
    __nv_bfloat16 h = __float2bfloat16_rn(v);
    g_c_hi[ci] = h;
    g_c_lo[ci] = __float2bfloat16_rn(v - __bfloat162float(h));
}

// ---------------- final layer: dot(256) + bias + sigmoid -------------------
__global__ void final_kernel(const float* __restrict__ W3, const float* __restrict__ b3,
                             float* __restrict__ out) {
    int gwarp = (blockIdx.x * blockDim.x + threadIdx.x) >> 5;
    int lane  = threadIdx.x & 31;
    if (gwarp >= Bsz) return;
    float s = 0.0f;
    #pragma unroll
    for (int k = lane; k < 256; k += 32)
        s += g_h2[(size_t)gwarp * 256 + k] * W3[k];
    #pragma unroll
    for (int o = 16; o; o >>= 1) s += __shfl_xor_sync(0xffffffffu, s, o);
    if (lane == 0) out[gwarp] = 1.0f / (1.0f + expf(-(s + b3[0])));
}

// ---------------- launch ----------------------------------------------------
extern "C" void kernel_launch(void* const* d_in, const int* in_sizes, int n_in,
                              void* d_out, int out_size) {
    const int*   item_id   = (const int*)  d_in[0];
    const float* x_d128    = (const float*)d_in[1];
    const int*   likes     = (const int*)  d_in[2];
    const int*   views     = (const int*)  d_in[3];
    const int*   item_seq  = (const int*)  d_in[4];
    const float* item_emb  = (const float*)d_in[5];
    const float* cate_emb  = (const float*)d_in[6];
    const float* mm_W      = (const float*)d_in[7];
    const float* mm_b      = (const float*)d_in[8];
    const float* ln_g      = (const float*)d_in[9];
    const float* ln_b      = (const float*)d_in[10];
    const float* se_W1     = (const float*)d_in[11];
    const float* se_b1     = (const float*)d_in[12];
    const float* se_W2     = (const float*)d_in[13];
    const float* se_b2     = (const float*)d_in[14];
    const float* bi_W      = (const float*)d_in[15];
    const float* mlp_W1    = (const float*)d_in[16];
    const float* mlp_b1    = (const float*)d_in[17];
    const float* bn1_g     = (const float*)d_in[18];
    const float* bn1_b     = (const float*)d_in[19];
    const float* bn1_rm    = (const float*)d_in[20];
    const float* bn1_rv    = (const float*)d_in[21];
    const float* mlp_W2    = (const float*)d_in[22];
    const float* mlp_b2    = (const float*)d_in[23];
    const float* bn2_g     = (const float*)d_in[24];
    const float* bn2_b     = (const float*)d_in[25];
    const float* bn2_rm    = (const float*)d_in[26];
    const float* bn2_rv    = (const float*)d_in[27];
    const float* mlp_W3    = (const float*)d_in[28];
    const float* mlp_b3    = (const float*)d_in[29];
    float*       out       = (float*)d_out;

    float *p_mm_pre, *p_xs, *p_xw, *p_h2;
    float *p_bn1_s, *p_bn1_t, *p_bn2_s, *p_bn2_t;
    __nv_bfloat16 *p_c_hi, *p_c_lo, *p_h1_hi, *p_h1_lo;
    __nv_bfloat16 *p_W1T_hi, *p_W1T_lo, *p_W2T_hi, *p_W2T_lo;
    cudaGetSymbolAddress((void**)&p_mm_pre, g_mm_pre);
    cudaGetSymbolAddress((void**)&p_xs,     g_xs);
    cudaGetSymbolAddress((void**)&p_xw,     g_xw);
    cudaGetSymbolAddress((void**)&p_h2,     g_h2);
    cudaGetSymbolAddress((void**)&p_c_hi,   g_c_hi);
    cudaGetSymbolAddress((void**)&p_c_lo,   g_c_lo);
    cudaGetSymbolAddress((void**)&p_h1_hi,  g_h1_hi);
    cudaGetSymbolAddress((void**)&p_h1_lo,  g_h1_lo);
    cudaGetSymbolAddress((void**)&p_W1T_hi, g_W1T_hi);
    cudaGetSymbolAddress((void**)&p_W1T_lo, g_W1T_lo);
    cudaGetSymbolAddress((void**)&p_W2T_hi, g_W2T_hi);
    cudaGetSymbolAddress((void**)&p_W2T_lo, g_W2T_lo);
    cudaGetSymbolAddress((void**)&p_bn1_s,  g_bn1_s);
    cudaGetSymbolAddress((void**)&p_bn1_t,  g_bn1_t);
    cudaGetSymbolAddress((void**)&p_bn2_s,  g_bn2_s);
    cudaGetSymbolAddress((void**)&p_bn2_t,  g_bn2_t);

    cudaFuncSetAttribute(mma_gemm<true>,  cudaFuncAttributeMaxDynamicSharedMemorySize, MMG_SMEM);
    cudaFuncSetAttribute(mma_gemm<false>, cudaFuncAttributeMaxDynamicSharedMemorySize, MMG_SMEM);

    // prep
    prep_bn_kernel<<<1, 512>>>(mlp_b1, bn1_g, bn1_b, bn1_rm, bn1_rv,
                               mlp_b2, bn2_g, bn2_b, bn2_rm, bn2_rv);
    prep_w1_kernel<<<(512 * KC + 255) / 256, 256>>>(mlp_W1);
    prep_w2_kernel<<<(256 * 512 + 255) / 256, 256>>>(mlp_W2);

    // mm_pre = item_emb_d128 @ mm_W + mm_b
    gemm_f32<false><<<dim3(128 / 64, Bsz / 128), 256>>>(
        x_d128, mm_W, p_mm_pre, Bsz, 128, 128, nullptr, mm_b);

    // per-row features -> xs (fp32), c_hi/lo[:, 0:640]
    features_kernel<<<Bsz, 128>>>(item_id, likes, views, item_seq,
                                  item_emb, cate_emb, ln_g, ln_b,
                                  se_W1, se_b1, se_W2, se_b2);

    // xw = xs @ bi_W   (M = B*6)
    gemm_f32<false><<<dim3(128 / 64, (Bsz * 6) / 128), 256>>>(
        p_xs, bi_W, p_xw, Bsz * 6, 128, 128, nullptr, nullptr);

    // pair products -> c_hi/lo[:, 640:1920]
    pairs_kernel<<<(Bsz * 10 * EDIM + 255) / 256, 256>>>();

    // h1 = relu(bn1(c @ W1c^T + b1))   -- mma.sync, K=1920, out bf16 split
    mma_gemm<true><<<dim3(512 / 128, Bsz / 128), 256, MMG_SMEM>>>(
        p_c_hi, p_c_lo, p_W1T_hi, p_W1T_lo, KC,
        p_bn1_s, p_bn1_t, nullptr, p_h1_hi, p_h1_lo, 512);

    // h2 = relu(bn2(h1 @ W2^T + b2))   -- mma.sync, K=512, out fp32
    mma_gemm<false><<<dim3(256 / 128, Bsz / 128), 256, MMG_SMEM>>>(
        p_h1_hi, p_h1_lo, p_W2T_hi, p_W2T_lo, 512,
        p_bn2_s, p_bn2_t, p_h2, nullptr, nullptr, 256);

    // logits -> sigmoid
    final_kernel<<<(Bsz * 32 + 255) / 256, 256>>>(mlp_W3, mlp_b3, out);
}

// round 4
// speedup vs baseline: 1.8784x; 1.1804x over previous
#include <cuda_runtime.h>
#include <cuda_bf16.h>
#include <math.h>
#include <stdint.h>

#define Bsz  16384
#define EDIM 128
#define HIST 50
#define KC   1920   // compact K for MLP1 (zero columns of c removed)
#define EPSF 1e-5f

// ---------------- scratch (device globals; no allocation allowed) ----------
__device__ float g_mm_pre[Bsz * EDIM];                       //  8.4 MB
__device__ float g_xs[Bsz * 4 * EDIM];                       // 33 MB (fields 1..4, for pair-i)
__device__ float g_xw[Bsz * 4 * EDIM];                       // 33 MB (fields 2..5, for pair-j)
__device__ __nv_bfloat16 g_xs4_hi[Bsz * 4 * EDIM];           // 16.8 MB (fields 2..5, xw GEMM A)
__device__ __nv_bfloat16 g_xs4_lo[Bsz * 4 * EDIM];
__device__ __nv_bfloat16 g_xd_hi[Bsz * EDIM];                //  4.2 MB (x_d128 split)
__device__ __nv_bfloat16 g_xd_lo[Bsz * EDIM];
__device__ __nv_bfloat16 g_c_hi[(size_t)Bsz * KC];           // 63 MB
__device__ __nv_bfloat16 g_c_lo[(size_t)Bsz * KC];
__device__ __nv_bfloat16 g_h1_hi[Bsz * 512];                 // 16.8 MB
__device__ __nv_bfloat16 g_h1_lo[Bsz * 512];
__device__ float g_h2[Bsz * 256];                            // 16.8 MB
__device__ __nv_bfloat16 g_W1T_hi[512 * KC];                 //  2 MB (N-major [512][1920])
__device__ __nv_bfloat16 g_W1T_lo[512 * KC];
__device__ __nv_bfloat16 g_W2T_hi[256 * 512];                // [256][512]
__device__ __nv_bfloat16 g_W2T_lo[256 * 512];
__device__ __nv_bfloat16 g_mmWT_hi[128 * 128], g_mmWT_lo[128 * 128];
__device__ __nv_bfloat16 g_biWT_hi[128 * 128], g_biWT_lo[128 * 128];
__device__ float g_bn1_s[512], g_bn1_t[512];
__device__ float g_bn2_s[256], g_bn2_t[256];

// surviving pairs: (i,j) in {(1,2),(1,3),(1,4),(1,5),(2,3),(2,4),(2,5),(3,4),(3,5),(4,5)}
__constant__ int c_I0[10] = {0,0,0,0,1,1,1,2,2,3};  // i-1 -> g_xs field
__constant__ int c_J2[10] = {0,1,2,3,1,2,3,2,3,3};  // j-2 -> g_xw field

// ================= PTX helpers (non-arch-specific only) =====================
__device__ __forceinline__ uint32_t smem_u32(const void* p) {
    uint32_t a;
    asm("{ .reg .u64 t; cvta.to.shared.u64 t, %1; cvt.u32.u64 %0, t; }"
        : "=r"(a) : "l"(p));
    return a;
}
__device__ __forceinline__ void cp_async16(uint32_t dst, const void* src) {
    asm volatile("cp.async.cg.shared.global [%0], [%1], 16;" :: "r"(dst), "l"(src));
}
#define CP_COMMIT() asm volatile("cp.async.commit_group;" ::: "memory")
#define CP_WAIT0()  asm volatile("cp.async.wait_group 0;" ::: "memory")
#define CP_WAIT1()  asm volatile("cp.async.wait_group 1;" ::: "memory")

__device__ __forceinline__ void ldsm_x4(uint32_t* r, uint32_t addr) {
    asm volatile("ldmatrix.sync.aligned.m8n8.x4.shared.b16 {%0,%1,%2,%3}, [%4];"
                 : "=r"(r[0]), "=r"(r[1]), "=r"(r[2]), "=r"(r[3]) : "r"(addr));
}
#define MMA_BF16(c, a, b0v, b1v) \
    asm volatile("mma.sync.aligned.m16n8k16.row.col.f32.bf16.bf16.f32 " \
        "{%0,%1,%2,%3}, {%4,%5,%6,%7}, {%8,%9}, {%0,%1,%2,%3};" \
        : "+f"((c)[0]), "+f"((c)[1]), "+f"((c)[2]), "+f"((c)[3]) \
        : "r"((a)[0]), "r"((a)[1]), "r"((a)[2]), "r"((a)[3]), "r"(b0v), "r"(b1v))

// ---------------- prep kernels ----------------------------------------------
__global__ void prep_bn_kernel(const float* __restrict__ b1, const float* __restrict__ g1,
                               const float* __restrict__ be1, const float* __restrict__ rm1,
                               const float* __restrict__ rv1,
                               const float* __restrict__ b2, const float* __restrict__ g2,
                               const float* __restrict__ be2, const float* __restrict__ rm2,
                               const float* __restrict__ rv2) {
    int i = blockIdx.x * blockDim.x + threadIdx.x;
    if (i < 512) {
        float s = g1[i] * rsqrtf(rv1[i] + EPSF);
        g_bn1_s[i] = s;
        g_bn1_t[i] = (b1[i] - rm1[i]) * s + be1[i];
    }
    if (i < 256) {
        float s = g2[i] * rsqrtf(rv2[i] + EPSF);
        g_bn2_s[i] = s;
        g_bn2_t[i] = (b2[i] - rm2[i]) * s + be2[i];
    }
}

// W1: compact rows + transpose to [N=512][K=1920], split bf16 hi/lo
__global__ void prep_w1_kernel(const float* __restrict__ W1) {
    int idx = blockIdx.x * blockDim.x + threadIdx.x;
    if (idx >= 512 * KC) return;
    int n = idx / KC;
    int k = idx % KC;
    int orig = (k < 640) ? (k + 128) : (k + 768);
    float v = W1[(size_t)orig * 512 + n];
    __nv_bfloat16 h = __float2bfloat16_rn(v);
    g_W1T_hi[idx] = h;
    g_W1T_lo[idx] = __float2bfloat16_rn(v - __bfloat162float(h));
}

// W2: transpose [512][256] -> [256][512], split bf16
__global__ void prep_w2_kernel(const float* __restrict__ W2) {
    int idx = blockIdx.x * blockDim.x + threadIdx.x;
    if (idx >= 256 * 512) return;
    int n = idx / 512;
    int k = idx % 512;
    float v = W2[(size_t)k * 256 + n];
    __nv_bfloat16 h = __float2bfloat16_rn(v);
    g_W2T_hi[idx] = h;
    g_W2T_lo[idx] = __float2bfloat16_rn(v - __bfloat162float(h));
}

// 128x128 transpose + split (mm_W and bi_W)
__global__ void prep_sq_kernel(const float* __restrict__ W,
                               __nv_bfloat16* __restrict__ Thi,
                               __nv_bfloat16* __restrict__ Tlo) {
    int idx = blockIdx.x * blockDim.x + threadIdx.x;
    if (idx >= 128 * 128) return;
    int n = idx >> 7;
    int k = idx & 127;
    float v = W[k * 128 + n];
    __nv_bfloat16 h = __float2bfloat16_rn(v);
    Thi[idx] = h;
    Tlo[idx] = __float2bfloat16_rn(v - __bfloat162float(h));
}

// split fp32 -> bf16 hi/lo (x_d128)
__global__ void split_xd_kernel(const float* __restrict__ x) {
    int idx = blockIdx.x * blockDim.x + threadIdx.x;
    if (idx >= Bsz * EDIM) return;
    float v = x[idx];
    __nv_bfloat16 h = __float2bfloat16_rn(v);
    g_xd_hi[idx] = h;
    g_xd_lo[idx] = __float2bfloat16_rn(v - __bfloat162float(h));
}

// ======== mma.sync bf16 split-3 GEMM: C = epi(A@B^T) ========================
// A (hi/lo bf16): M x K row-major. B (hi/lo bf16): Ntot x K row-major.
// CTA tile 128x128, 8 warps (4m x 2n), BK=32, 2-stage cp.async, 2 CTAs/SM.
// MODE: 0 = fp32 plain (xw); 1 = fp32 + shift (mm);
//       2 = fp32 + scale/shift + relu (h2); 3 = bf16-split + scale/shift + relu (h1)
#define MMG_LDS    40                       // bf16 elems per smem row (32 + 8 pad)
#define MMG_ARR    (128 * MMG_LDS * 2)      // 10240 B per operand tile
#define MMG_STAGE  (4 * MMG_ARR)            // 40960 B
#define MMG_SMEM   (2 * MMG_STAGE)          // 81920 B

template <int MODE>
__global__ void __launch_bounds__(256, 2)
mma_gemm(const __nv_bfloat16* __restrict__ Ah, const __nv_bfloat16* __restrict__ Al,
         const __nv_bfloat16* __restrict__ Bh, const __nv_bfloat16* __restrict__ Bl,
         int K,
         const float* __restrict__ scale, const float* __restrict__ shift,
         float* __restrict__ Cf, __nv_bfloat16* __restrict__ Chi,
         __nv_bfloat16* __restrict__ Clo, int ldC) {
    extern __shared__ char smem[];
    const uint32_t sbase = smem_u32(smem);
    const int tid    = threadIdx.x;
    const int wid    = tid >> 5;
    const int lane   = tid & 31;
    const int warp_m = wid & 3;          // 0..3 -> 32 rows each
    const int warp_n = wid >> 2;         // 0..1 -> 64 cols each
    const int m0     = blockIdx.y * 128;
    const int bcol   = blockIdx.x * 128;
    const int nch    = K >> 5;           // BK = 32

    float acc[2][8][4];
    #pragma unroll
    for (int a = 0; a < 2; a++)
        #pragma unroll
        for (int b = 0; b < 8; b++)
            #pragma unroll
            for (int c = 0; c < 4; c++) acc[a][b][c] = 0.0f;

    // ---- stage loader: 2048 16B-chunks, 8 per thread ----
    auto load_stage = [&](int st, int k0) {
        const uint32_t sdst = sbase + st * MMG_STAGE;
        #pragma unroll
        for (int i = 0; i < 8; i++) {
            int c   = tid + i * 256;
            int a   = c >> 9;            // operand array 0..3 (uniform per i)
            int idx = c & 511;
            int r   = idx >> 2;
            int cc  = idx & 3;
            const __nv_bfloat16* g;
            if (a < 2) {
                g = (a == 0 ? Ah : Al) + (size_t)(m0 + r) * K + k0 + cc * 8;
            } else {
                g = (a == 2 ? Bh : Bl) + (size_t)(bcol + r) * K + k0 + cc * 8;
            }
            cp_async16(sdst + a * MMG_ARR + r * (MMG_LDS * 2) + cc * 16, g);
        }
        CP_COMMIT();
    };

    load_stage(0, 0);

    const int lrow = lane & 15;
    const int lcol = lane >> 4;

    for (int ch = 0; ch < nch; ch++) {
        if (ch + 1 < nch) {
            load_stage((ch + 1) & 1, (ch + 1) << 5);
            CP_WAIT1();
        } else {
            CP_WAIT0();
        }
        __syncthreads();

        const uint32_t sa_hi = sbase + (ch & 1) * MMG_STAGE;
        const uint32_t sa_lo = sa_hi + MMG_ARR;
        const uint32_t sb_hi = sa_hi + 2 * MMG_ARR;
        const uint32_t sb_lo = sa_hi + 3 * MMG_ARR;

        #pragma unroll
        for (int kk = 0; kk < 2; kk++) {
            uint32_t ah[2][4], al[2][4];
            #pragma unroll
            for (int mt = 0; mt < 2; mt++) {
                uint32_t off = (uint32_t)((warp_m * 32 + mt * 16 + lrow) * (MMG_LDS * 2)
                               + kk * 32 + lcol * 16);
                ldsm_x4(ah[mt], sa_hi + off);
                ldsm_x4(al[mt], sa_lo + off);
            }
            // loop q, loading B frags just-in-time (keeps live regs < 128 for occ=2)
            #pragma unroll
            for (int q = 0; q < 4; q++) {
                uint32_t bh[4], bl[4];
                uint32_t off = (uint32_t)((warp_n * 64 + q * 16 + lrow) * (MMG_LDS * 2)
                               + kk * 32 + lcol * 16);
                ldsm_x4(bh, sb_hi + off);
                ldsm_x4(bl, sb_lo + off);
                #pragma unroll
                for (int mt = 0; mt < 2; mt++) {
                    #pragma unroll
                    for (int sl = 0; sl < 2; sl++) {
                        MMA_BF16(acc[mt][q * 2 + sl], ah[mt], bh[sl], bh[sl + 2]); // hi*hi
                        MMA_BF16(acc[mt][q * 2 + sl], ah[mt], bl[sl], bl[sl + 2]); // hi*lo
                        MMA_BF16(acc[mt][q * 2 + sl], al[mt], bh[sl], bh[sl + 2]); // lo*hi
                    }
                }
            }
        }
        __syncthreads();
    }

    // ---- fused epilogue ----
    #pragma unroll
    for (int mt = 0; mt < 2; mt++) {
        const int rbase = m0 + warp_m * 32 + mt * 16 + (lane >> 2);
        #pragma unroll
        for (int nt = 0; nt < 8; nt++) {
            const int col = bcol + warp_n * 64 + nt * 8 + (lane & 3) * 2;
            float s0 = 1.0f, s1 = 1.0f, t0 = 0.0f, t1 = 0.0f;
            if (MODE >= 2) { s0 = scale[col]; s1 = scale[col + 1]; }
            if (MODE >= 1) { t0 = shift[col]; t1 = shift[col + 1]; }
            #pragma unroll
            for (int h = 0; h < 2; h++) {
                const size_t row = (size_t)(rbase + h * 8);
                float v0 = acc[mt][nt][h * 2 + 0];
                float v1 = acc[mt][nt][h * 2 + 1];
                if (MODE >= 2) {
                    v0 = fmaxf(v0 * s0 + t0, 0.0f);
                    v1 = fmaxf(v1 * s1 + t1, 0.0f);
                } else if (MODE == 1) {
                    v0 += t0; v1 += t1;
                }
                if (MODE == 3) {
                    __nv_bfloat16 h0 = __float2bfloat16_rn(v0);
                    __nv_bfloat16 h1 = __float2bfloat16_rn(v1);
                    __nv_bfloat162 hv; hv.x = h0; hv.y = h1;
                    __nv_bfloat162 lv;
                    lv.x = __float2bfloat16_rn(v0 - __bfloat162float(h0));
                    lv.y = __float2bfloat16_rn(v1 - __bfloat162float(h1));
                    *(__nv_bfloat162*)&Chi[row * ldC + col] = hv;
                    *(__nv_bfloat162*)&Clo[row * ldC + col] = lv;
                } else {
                    float2 fv; fv.x = v0; fv.y = v1;
                    *(float2*)&Cf[row * ldC + col] = fv;
                }
            }
        }
    }
}

// ---------------- per-row feature construction ------------------------------
__device__ __forceinline__ float block_sum_128(float v, float* sred) {
    int lane = threadIdx.x & 31, wid = threadIdx.x >> 5;
    #pragma unroll
    for (int o = 16; o; o >>= 1) v += __shfl_xor_sync(0xffffffffu, v, o);
    if (lane == 0) sred[wid] = v;
    __syncthreads();
    float s = sred[0] + sred[1] + sred[2] + sred[3];
    __syncthreads();
    return s;
}

__global__ void features_kernel(const int* __restrict__ item_id,
                                const int* __restrict__ likes,
                                const int* __restrict__ views,
                                const int* __restrict__ item_seq,
                                const float* __restrict__ item_emb,
                                const float* __restrict__ cate_emb,
                                const float* __restrict__ ln_g,
                                const float* __restrict__ ln_b,
                                const float* __restrict__ se_W1,
                                const float* __restrict__ se_b1,
                                const float* __restrict__ se_W2,
                                const float* __restrict__ se_b2) {
    __shared__ float sred[4];
    const int b = blockIdx.x;
    const int e = threadIdx.x;

    float mmv = g_mm_pre[(size_t)b * EDIM + e];
    float mu  = block_sum_128(mmv, sred) * (1.0f / 128.0f);
    float d   = mmv - mu;
    float var = block_sum_128(d * d, sred) * (1.0f / 128.0f);
    float mm  = fmaxf(d * rsqrtf(var + EPSF) * ln_g[e] + ln_b[e], 0.0f);

    int   id   = item_id[b];
    float item = (id == 0) ? 0.0f : item_emb[(size_t)id * EDIM + e];
    float like = cate_emb[(size_t)likes[b] * EDIM + e];
    float view = cate_emb[(size_t)views[b] * EDIM + e];

    float hsum = 0.0f;
    int   cnt  = 0;
    #pragma unroll 5
    for (int t = 0; t < HIST; t++) {
        int s = item_seq[(size_t)b * HIST + t];
        if (s != 0) { hsum += item_emb[(size_t)s * EDIM + e]; cnt++; }
    }
    float hist = hsum / (float)(cnt > 1 ? cnt : 1);

    float x[6] = {0.0f, like, view, item, mm, hist};

    float z[6];
    z[0] = 0.0f;
    #pragma unroll
    for (int f = 1; f < 6; f++) z[f] = block_sum_128(x[f], sred) * (1.0f / 128.0f);

    float w[6];
    {
        float h[3];
        #pragma unroll
        for (int j = 0; j < 3; j++) {
            float s = se_b1[j];
            #pragma unroll
            for (int f = 0; f < 6; f++) s += z[f] * se_W1[f * 3 + j];
            h[j] = fmaxf(s, 0.0f);
        }
        #pragma unroll
        for (int f = 0; f < 6; f++) {
            float s = se_b2[f];
            #pragma unroll
            for (int j = 0; j < 3; j++) s += h[j] * se_W2[j * 6 + f];
            w[f] = 1.0f / (1.0f + expf(-s));
        }
    }

    #pragma unroll
    for (int f = 1; f < 6; f++) {
        float xv = x[f] * w[f];
        // c columns [0, 640): xs fields 1..5 split
        size_t ci = (size_t)b * KC + (f - 1) * EDIM + e;
        __nv_bfloat16 h = __float2bfloat16_rn(xv);
        g_c_hi[ci] = h;
        __nv_bfloat16 l = __float2bfloat16_rn(xv - __bfloat162float(h));
        g_c_lo[ci] = l;
        // pair-i operand (fields 1..4), fp32
        if (f <= 4)
            g_xs[((size_t)b * 4 + (f - 1)) * EDIM + e] = xv;
        // xw GEMM input (fields 2..5), bf16 split (reuse h/l)
        if (f >= 2) {
            size_t si = ((size_t)b * 4 + (f - 2)) * EDIM + e;
            g_xs4_hi[si] = h;
            g_xs4_lo[si] = l;
        }
    }
}

// ---------------- bilinear pair products (non-zero pairs only) -------------
__global__ void pairs_kernel() {
    int idx = blockIdx.x * blockDim.x + threadIdx.x;   // over Bsz*10*128
    if (idx >= Bsz * 10 * EDIM) return;
    int e  = idx & 127;
    int pr = (idx >> 7) % 10;
    int b  = idx / (10 * EDIM);
    float v = g_xs[((size_t)b * 4 + c_I0[pr]) * EDIM + e] *
              g_xw[((size_t)b * 4 + c_J2[pr]) * EDIM + e];
    size_t ci = (size_t)b * KC + 640 + pr * EDIM + e;
    __nv_bfloat16 h = __float2bfloat16_rn(v);
    g_c_hi[ci] = h;
    g_c_lo[ci] = __float2bfloat16_rn(v - __bfloat162float(h));
}

// ---------------- final layer: dot(256) + bias + sigmoid -------------------
__global__ void final_kernel(const float* __restrict__ W3, const float* __restrict__ b3,
                             float* __restrict__ out) {
    int gwarp = (blockIdx.x * blockDim.x + threadIdx.x) >> 5;
    int lane  = threadIdx.x & 31;
    if (gwarp >= Bsz) return;
    float s = 0.0f;
    #pragma unroll
    for (int k = lane; k < 256; k += 32)
        s += g_h2[(size_t)gwarp * 256 + k] * W3[k];
    #pragma unroll
    for (int o = 16; o; o >>= 1) s += __shfl_xor_sync(0xffffffffu, s, o);
    if (lane == 0) out[gwarp] = 1.0f / (1.0f + expf(-(s + b3[0])));
}

// ---------------- launch ----------------------------------------------------
extern "C" void kernel_launch(void* const* d_in, const int* in_sizes, int n_in,
                              void* d_out, int out_size) {
    const int*   item_id   = (const int*)  d_in[0];
    const float* x_d128    = (const float*)d_in[1];
    const int*   likes     = (const int*)  d_in[2];
    const int*   views     = (const int*)  d_in[3];
    const int*   item_seq  = (const int*)  d_in[4];
    const float* item_emb  = (const float*)d_in[5];
    const float* cate_emb  = (const float*)d_in[6];
    const float* mm_W      = (const float*)d_in[7];
    const float* mm_b      = (const float*)d_in[8];
    const float* ln_g      = (const float*)d_in[9];
    const float* ln_b      = (const float*)d_in[10];
    const float* se_W1     = (const float*)d_in[11];
    const float* se_b1     = (const float*)d_in[12];
    const float* se_W2     = (const float*)d_in[13];
    const float* se_b2     = (const float*)d_in[14];
    const float* bi_W      = (const float*)d_in[15];
    const float* mlp_W1    = (const float*)d_in[16];
    const float* mlp_b1    = (const float*)d_in[17];
    const float* bn1_g     = (const float*)d_in[18];
    const float* bn1_b     = (const float*)d_in[19];
    const float* bn1_rm    = (const float*)d_in[20];
    const float* bn1_rv    = (const float*)d_in[21];
    const float* mlp_W2    = (const float*)d_in[22];
    const float* mlp_b2    = (const float*)d_in[23];
    const float* bn2_g     = (const float*)d_in[24];
    const float* bn2_b     = (const float*)d_in[25];
    const float* bn2_rm    = (const float*)d_in[26];
    const float* bn2_rv    = (const float*)d_in[27];
    const float* mlp_W3    = (const float*)d_in[28];
    const float* mlp_b3    = (const float*)d_in[29];
    float*       out       = (float*)d_out;

    float *p_mm_pre, *p_xs, *p_xw, *p_h2;
    float *p_bn1_s, *p_bn1_t, *p_bn2_s, *p_bn2_t;
    __nv_bfloat16 *p_c_hi, *p_c_lo, *p_h1_hi, *p_h1_lo;
    __nv_bfloat16 *p_W1T_hi, *p_W1T_lo, *p_W2T_hi, *p_W2T_lo;
    __nv_bfloat16 *p_xs4_hi, *p_xs4_lo, *p_xd_hi, *p_xd_lo;
    __nv_bfloat16 *p_mmWT_hi, *p_mmWT_lo, *p_biWT_hi, *p_biWT_lo;
    cudaGetSymbolAddress((void**)&p_mm_pre,  g_mm_pre);
    cudaGetSymbolAddress((void**)&p_xs,      g_xs);
    cudaGetSymbolAddress((void**)&p_xw,      g_xw);
    cudaGetSymbolAddress((void**)&p_h2,      g_h2);
    cudaGetSymbolAddress((void**)&p_c_hi,    g_c_hi);
    cudaGetSymbolAddress((void**)&p_c_lo,    g_c_lo);
    cudaGetSymbolAddress((void**)&p_h1_hi,   g_h1_hi);
    cudaGetSymbolAddress((void**)&p_h1_lo,   g_h1_lo);
    cudaGetSymbolAddress((void**)&p_W1T_hi,  g_W1T_hi);
    cudaGetSymbolAddress((void**)&p_W1T_lo,  g_W1T_lo);
    cudaGetSymbolAddress((void**)&p_W2T_hi,  g_W2T_hi);
    cudaGetSymbolAddress((void**)&p_W2T_lo,  g_W2T_lo);
    cudaGetSymbolAddress((void**)&p_xs4_hi,  g_xs4_hi);
    cudaGetSymbolAddress((void**)&p_xs4_lo,  g_xs4_lo);
    cudaGetSymbolAddress((void**)&p_xd_hi,   g_xd_hi);
    cudaGetSymbolAddress((void**)&p_xd_lo,   g_xd_lo);
    cudaGetSymbolAddress((void**)&p_mmWT_hi, g_mmWT_hi);
    cudaGetSymbolAddress((void**)&p_mmWT_lo, g_mmWT_lo);
    cudaGetSymbolAddress((void**)&p_biWT_hi, g_biWT_hi);
    cudaGetSymbolAddress((void**)&p_biWT_lo, g_biWT_lo);
    cudaGetSymbolAddress((void**)&p_bn1_s,   g_bn1_s);
    cudaGetSymbolAddress((void**)&p_bn1_t,   g_bn1_t);
    cudaGetSymbolAddress((void**)&p_bn2_s,   g_bn2_s);
    cudaGetSymbolAddress((void**)&p_bn2_t,   g_bn2_t);

    cudaFuncSetAttribute(mma_gemm<0>, cudaFuncAttributeMaxDynamicSharedMemorySize, MMG_SMEM);
    cudaFuncSetAttribute(mma_gemm<1>, cudaFuncAttributeMaxDynamicSharedMemorySize, MMG_SMEM);
    cudaFuncSetAttribute(mma_gemm<2>, cudaFuncAttributeMaxDynamicSharedMemorySize, MMG_SMEM);
    cudaFuncSetAttribute(mma_gemm<3>, cudaFuncAttributeMaxDynamicSharedMemorySize, MMG_SMEM);

    // prep (weights + BN folding + input split)
    prep_bn_kernel<<<1, 512>>>(mlp_b1, bn1_g, bn1_b, bn1_rm, bn1_rv,
                               mlp_b2, bn2_g, bn2_b, bn2_rm, bn2_rv);
    prep_w1_kernel<<<(512 * KC + 255) / 256, 256>>>(mlp_W1);
    prep_w2_kernel<<<(256 * 512 + 255) / 256, 256>>>(mlp_W2);
    prep_sq_kernel<<<(128 * 128 + 255) / 256, 256>>>(mm_W, p_mmWT_hi, p_mmWT_lo);
    prep_sq_kernel<<<(128 * 128 + 255) / 256, 256>>>(bi_W, p_biWT_hi, p_biWT_lo);
    split_xd_kernel<<<(Bsz * EDIM + 255) / 256, 256>>>(x_d128);

    // mm_pre = item_emb_d128 @ mm_W + mm_b   (mma, MODE 1: +shift)
    mma_gemm<1><<<dim3(1, Bsz / 128), 256, MMG_SMEM>>>(
        p_xd_hi, p_xd_lo, p_mmWT_hi, p_mmWT_lo, 128,
        nullptr, mm_b, p_mm_pre, nullptr, nullptr, 128);

    // per-row features -> c[:,0:640] split, xs fp32 (fields 1..4), xs4 split (fields 2..5)
    features_kernel<<<Bsz, 128>>>(item_id, likes, views, item_seq,
                                  item_emb, cate_emb, ln_g, ln_b,
                                  se_W1, se_b1, se_W2, se_b2);

    // xw = xs4 @ bi_W   (M = B*4, mma MODE 0)
    mma_gemm<0><<<dim3(1, (Bsz * 4) / 128), 256, MMG_SMEM>>>(
        p_xs4_hi, p_xs4_lo, p_biWT_hi, p_biWT_lo, 128,
        nullptr, nullptr, p_xw, nullptr, nullptr, 128);

    // pair products -> c[:, 640:1920]
    pairs_kernel<<<(Bsz * 10 * EDIM + 255) / 256, 256>>>();

    // h1 = relu(bn1(c @ W1c^T + b1))   (mma MODE 3, K=1920, out bf16 split)
    mma_gemm<3><<<dim3(512 / 128, Bsz / 128), 256, MMG_SMEM>>>(
        p_c_hi, p_c_lo, p_W1T_hi, p_W1T_lo, KC,
        p_bn1_s, p_bn1_t, nullptr, p_h1_hi, p_h1_lo, 512);

    // h2 = relu(bn2(h1 @ W2^T + b2))   (mma MODE 2, K=512, out fp32)
    mma_gemm<2><<<dim3(256 / 128, Bsz / 128), 256, MMG_SMEM>>>(
        p_h1_hi, p_h1_lo, p_W2T_hi, p_W2T_lo, 512,
        p_bn2_s, p_bn2_t, p_h2, nullptr, nullptr, 256);

    // logits -> sigmoid
    final_kernel<<<(Bsz * 32 + 255) / 256, 256>>>(mlp_W3, mlp_b3, out);
}